// round 2
// baseline (speedup 1.0000x reference)
#include <cuda_runtime.h>
#include <cstdint>

#define DP    512     // padded state width
#define D     500     // real state width (M+N)
#define MDIM  250
#define NDIM  250
#define BATCH 1024
#define HDIM  512
#define ITERS 1000

typedef unsigned long long ull;

// ---------------- device scratch (allocation-free) ----------------
__device__ float g_P [DP*DP];       // P[i*512+j] = I - (Ainv@Aaug)^T, zero-padded
__device__ float g_h1[BATCH*HDIM];
__device__ float g_h2[BATCH*HDIM];
__device__ float g_y [BATCH*DP];    // MLP output, cols 500..511 zero
__device__ float g_q [BATCH*DP];    // bv @ Ainv^T, cols 500..511 zero

// ---------------- f32x2 helpers (Blackwell packed fp32) ----------------
__device__ __forceinline__ void ffma2(ull &d, ull a, ull b) {
    asm("fma.rn.f32x2 %0, %1, %2, %0;" : "+l"(d) : "l"(a), "l"(b));
}
__device__ __forceinline__ ull addx2(ull a, ull b) {
    ull d; asm("add.rn.f32x2 %0, %1, %2;" : "=l"(d) : "l"(a), "l"(b)); return d;
}
__device__ __forceinline__ float2 unpk(ull a) {
    float2 f; asm("mov.b64 {%0,%1}, %2;" : "=f"(f.x), "=f"(f.y) : "l"(a)); return f;
}

// ---------------- P = I - (Aaug_inv @ Aaug)^T ----------------
// P[i][j] = (i==j) - sum_k Aaug[k*500+i] * Ainv[j*250+k]; zero outside 500x500.
__global__ void computeP(const float* __restrict__ Aaug, const float* __restrict__ Ainv) {
    int idx = blockIdx.x * 256 + threadIdx.x;
    int i = idx & (DP - 1);   // fastest -> coalesced Aaug reads
    int j = idx >> 9;         // uniform per warp -> broadcast Ainv reads
    float acc = 0.f;
    if (i < D && j < D) {
        acc = (i == j) ? 1.f : 0.f;
        for (int k = 0; k < MDIM; ++k)
            acc -= Aaug[k * D + i] * Ainv[j * MDIM + k];
    }
    g_P[i * DP + j] = acc;
}

// ---------------- generic small GEMM: C = act(A@B + bias), padded ----------------
#define FLAG_RELU   1
#define FLAG_TRANSB 2
#define FLAG_CONCAT 4
__global__ void gemm16(const float* __restrict__ A, const float* __restrict__ A2,
                       const float* __restrict__ B, const float* __restrict__ bias,
                       float* __restrict__ C, int K, int Nr, int ldc, int flags) {
    __shared__ float As[16][16];
    __shared__ float Bs[16][17];
    int tx = threadIdx.x, ty = threadIdx.y;
    int m = blockIdx.y * 16 + ty;
    int n = blockIdx.x * 16 + tx;
    float acc = 0.f;
    for (int k0 = 0; k0 < K; k0 += 16) {
        int ka = k0 + tx;
        float av = 0.f;
        if (ka < K) {
            if (flags & FLAG_CONCAT) av = (ka < MDIM) ? A[m * MDIM + ka] : A2[m * MDIM + ka - MDIM];
            else                     av = A[m * K + ka];
        }
        As[ty][tx] = av;
        int kb = k0 + ty;
        float bv = 0.f;
        if (kb < K && n < Nr) bv = (flags & FLAG_TRANSB) ? B[n * K + kb] : B[kb * Nr + n];
        Bs[ty][tx] = bv;
        __syncthreads();
#pragma unroll
        for (int kk = 0; kk < 16; ++kk) acc += As[ty][kk] * Bs[kk][tx];
        __syncthreads();
    }
    if (n < ldc) {
        float v = 0.f;
        if (n < Nr) {
            v = acc + (bias ? bias[n] : 0.f);
            if (flags & FLAG_RELU) v = fmaxf(v, 0.f);
        }
        C[m * ldc + n] = v;   // pads cols [Nr, ldc) with 0
    }
}

// ---------------- persistent iteration kernel ----------------
// Grid: 128 CTAs x 128 threads. CTA owns 8 batch rows.
// Warp w: group g=w>>1 (rows 4g..4g+3), K-half kh=w&1 (k in [256kh, 256kh+256)).
// Lane owns 16 columns j0=lane*16..j0+15 (8 f32x2 column-pairs).
// s kept duplicated {v,v} in smem so FFMA2 needs no per-i packing.
#define SMEM_BYTES (32768 /*sdup*/ + 16384 /*red*/ + 16384 /*y*/ + 16384 /*q*/)

__global__ void __launch_bounds__(128, 1) iterate_kernel(float* __restrict__ out) {
    extern __shared__ char smem[];
    ull*   sdup = (ull*)smem;                         // [512][8] : {s,s} per (i,row)
    ull*   red  = (ull*)(smem + 32768);               // [8][256] : K-split partials
    float* yv   = (float*)(smem + 32768 + 16384);     // [8][512]
    float* qv   = yv + 8 * DP;                        // [8][512]

    const int tid  = threadIdx.x;
    const int warp = tid >> 5, lane = tid & 31;
    const int g = warp >> 1, kh = warp & 1;
    const int rb = g * 4;
    const int j0 = lane * 16;
    const int rowbase = blockIdx.x * 8;

    { // stage y, q; zero s
        const float4* ys = (const float4*)(g_y + rowbase * DP);
        const float4* qs = (const float4*)(g_q + rowbase * DP);
        float4* yd = (float4*)yv; float4* qd = (float4*)qv;
        for (int i = tid; i < 8 * DP / 4; i += 128) { yd[i] = ys[i]; qd[i] = qs[i]; }
        for (int i = tid; i < 8 * DP; i += 128) sdup[i] = 0ull;
    }
    __syncthreads();

    const float OMEGA = 1.8f, TWOSIG = 0.2f, INVC = 1.0f / 1.2f;
    const int kbeg = kh * 256;

    for (int it = 0; it <= ITERS; ++it) {
        // ---- GEMM partial: acc[r][cp] over this warp's K-half ----
        ull acc[4][8];
#pragma unroll
        for (int r = 0; r < 4; ++r)
#pragma unroll
            for (int c = 0; c < 8; ++c) acc[r][c] = 0ull;

        const float* Pb = g_P + j0;
#pragma unroll 2
        for (int i = kbeg; i < kbeg + 256; ++i) {
            ulonglong2 sa = *(const ulonglong2*)&sdup[i * 8 + rb];
            ulonglong2 sb = *(const ulonglong2*)&sdup[i * 8 + rb + 2];
            const ulonglong2* pr = (const ulonglong2*)(Pb + i * DP);
            ulonglong2 p0 = pr[0], p1 = pr[1], p2 = pr[2], p3 = pr[3];
            ull p[8] = {p0.x, p0.y, p1.x, p1.y, p2.x, p2.y, p3.x, p3.y};
#pragma unroll
            for (int c = 0; c < 8; ++c) {
                ffma2(acc[0][c], sa.x, p[c]);
                ffma2(acc[1][c], sa.y, p[c]);
                ffma2(acc[2][c], sb.x, p[c]);
                ffma2(acc[3][c], sb.y, p[c]);
            }
        }

        // ---- exchange: I store the 2 rows I don't keep; partner stores mine ----
        const int oth = 1 - kh;
#pragma unroll
        for (int rr = 0; rr < 2; ++rr) {
            ulonglong2* d2 = (ulonglong2*)&red[(warp * 2 + rr) * 256 + lane * 8];
#pragma unroll
            for (int c = 0; c < 4; ++c) {
                ulonglong2 v; v.x = acc[oth * 2 + rr][2 * c]; v.y = acc[oth * 2 + rr][2 * c + 1];
                d2[c] = v;
            }
        }
        __syncthreads();
        const int partner = g * 2 + oth;
        ull zacc[2][8];
#pragma unroll
        for (int rr = 0; rr < 2; ++rr) {
            const ull* src = &red[(partner * 2 + rr) * 256 + lane * 8];
#pragma unroll
            for (int c = 0; c < 8; ++c) zacc[rr][c] = addx2(acc[kh * 2 + rr][c], src[c]);
        }

        if (it == ITERS) {   // final proj_pinv -> output
#pragma unroll
            for (int rr = 0; rr < 2; ++rr) {
                int r = rb + kh * 2 + rr;
                int gr = rowbase + r;
#pragma unroll
                for (int c = 0; c < 8; ++c) {
                    float2 f = unpk(zacc[rr][c]);
                    int j = j0 + 2 * c;
                    if (j     < D) out[gr * D + j]     = f.x + qv[r * DP + j];
                    if (j + 1 < D) out[gr * D + j + 1] = f.y + qv[r * DP + j + 1];
                }
            }
            break;
        }

        // ---- elementwise + SOC projection + s update (2 rows per warp) ----
#pragma unroll
        for (int rr = 0; rr < 2; ++rr) {
            int r = rb + kh * 2 + rr;
            float z[16], tp[16];
#pragma unroll
            for (int c = 0; c < 8; ++c) {
                float2 f = unpk(zacc[rr][c]);
                z[2 * c]     = f.x + qv[r * DP + j0 + 2 * c];
                z[2 * c + 1] = f.y + qv[r * DP + j0 + 2 * c + 1];
            }
#pragma unroll
            for (int c = 0; c < 16; ++c) {
                int j = j0 + c;
                float sv = *(const float*)&sdup[j * 8 + r];
                tp[c] = (2.f * z[c] - sv - TWOSIG * yv[r * DP + j]) * INVC;
            }
            // ||u||^2 over j in [250, 499)
            float part = 0.f;
#pragma unroll
            for (int c = 0; c < 16; ++c) {
                int j = j0 + c;
                if (j >= NDIM && j < D - 1) part += tp[c] * tp[c];
            }
#pragma unroll
            for (int o = 16; o > 0; o >>= 1) part += __shfl_xor_sync(0xffffffffu, part, o);
            float nrm  = sqrtf(part);
            float tval = __shfl_sync(0xffffffffu, tp[3], 31);   // j=499 lives at lane31,c=3
            float f3 = 0.5f * (tval + nrm);
            float fu = f3 / (nrm + 1e-12f);
            bool case1 = (nrm <= tval);
            bool case2 = (!case1) && (nrm <= -tval);
#pragma unroll
            for (int c = 0; c < 16; ++c) {
                int j = j0 + c;
                float tk;
                if      (j < NDIM)   tk = tp[c];
                else if (j < D - 1)  tk = case1 ? tp[c] : (case2 ? 0.f : fu * tp[c]);
                else if (j == D - 1) tk = case1 ? tp[c] : (case2 ? 0.f : f3);
                else                 tk = 0.f;
                float sv = *(const float*)&sdup[j * 8 + r];
                float sn = sv + OMEGA * (tk - z[c]);
                float2 w; w.x = sn; w.y = sn;
                *((float2*)&sdup[j * 8 + r]) = w;
            }
        }
        __syncthreads();
    }
}

// ---------------- launch ----------------
extern "C" void kernel_launch(void* const* d_in, const int* in_sizes, int n_in,
                              void* d_out, int out_size) {
    const float* b    = (const float*)d_in[0];
    const float* c    = (const float*)d_in[1];
    const float* W1   = (const float*)d_in[2];
    const float* b1   = (const float*)d_in[3];
    const float* W2   = (const float*)d_in[4];
    const float* b2   = (const float*)d_in[5];
    const float* W3   = (const float*)d_in[6];
    const float* b3   = (const float*)d_in[7];
    const float* Aaug = (const float*)d_in[8];
    const float* Ainv = (const float*)d_in[9];
    float* out = (float*)d_out;

    void *p;
    cudaGetSymbolAddress(&p, g_h1); float* h1 = (float*)p;
    cudaGetSymbolAddress(&p, g_h2); float* h2 = (float*)p;
    cudaGetSymbolAddress(&p, g_y ); float* yy = (float*)p;
    cudaGetSymbolAddress(&p, g_q ); float* qq = (float*)p;

    computeP<<<(DP * DP) / 256, 256>>>(Aaug, Ainv);

    dim3 tb(16, 16);
    // h1 = relu(concat(b,c) @ W1 + b1)
    gemm16<<<dim3(HDIM / 16, BATCH / 16), tb>>>(b, c, W1, b1, h1, 500, HDIM, HDIM, FLAG_RELU | FLAG_CONCAT);
    // h2 = relu(h1 @ W2 + b2)
    gemm16<<<dim3(HDIM / 16, BATCH / 16), tb>>>(h1, nullptr, W2, b2, h2, HDIM, HDIM, HDIM, FLAG_RELU);
    // y = h2 @ W3 + b3   (padded to 512)
    gemm16<<<dim3(DP / 16, BATCH / 16), tb>>>(h2, nullptr, W3, b3, yy, HDIM, D, DP, 0);
    // q = bv @ Ainv^T    (padded to 512)
    gemm16<<<dim3(DP / 16, BATCH / 16), tb>>>(b, nullptr, Ainv, nullptr, qq, MDIM, D, DP, FLAG_TRANSB);

    cudaFuncSetAttribute(iterate_kernel, cudaFuncAttributeMaxDynamicSharedMemorySize, SMEM_BYTES);
    iterate_kernel<<<BATCH / 8, 128, SMEM_BYTES>>>(out);
}

// round 7
// speedup vs baseline: 4.0371x; 4.0371x over previous
#include <cuda_runtime.h>
#include <cstdint>

#define DP    512     // padded state width
#define D     500     // real state width (M+N)
#define MDIM  250
#define NDIM  250
#define BATCH 1024
#define HDIM  512
#define ITERS 1000
#define SROW  9       // ull per state column (8 rows + 1 pad) -> 2-way store conflicts only

typedef unsigned long long ull;

// ---------------- device scratch (allocation-free) ----------------
__device__ float g_P [DP*DP];       // P[i*512+j] = I - (Ainv@Aaug)^T, zero-padded
__device__ float g_h1[BATCH*HDIM];
__device__ float g_h2[BATCH*HDIM];
__device__ float g_y [BATCH*DP];    // MLP output, cols 500..511 zero
__device__ float g_q [BATCH*DP];    // bv @ Ainv^T, cols 500..511 zero

// ---------------- f32x2 helpers ----------------
__device__ __forceinline__ void ffma2(ull &d, ull a, ull b) {
    asm("fma.rn.f32x2 %0, %1, %2, %0;" : "+l"(d) : "l"(a), "l"(b));
}
__device__ __forceinline__ float2 unpk(ull a) {
    float2 f; asm("mov.b64 {%0,%1}, %2;" : "=f"(f.x), "=f"(f.y) : "l"(a)); return f;
}
__device__ __forceinline__ ull dup2(float v) {
    ull d; asm("mov.b64 %0, {%1,%1};" : "=l"(d) : "f"(v)); return d;
}

// ---------------- P = I - (Aaug_inv @ Aaug)^T ----------------
__global__ void computeP(const float* __restrict__ Aaug, const float* __restrict__ Ainv) {
    int idx = blockIdx.x * 256 + threadIdx.x;
    int i = idx & (DP - 1);
    int j = idx >> 9;
    float acc = 0.f;
    if (i < D && j < D) {
        acc = (i == j) ? 1.f : 0.f;
        for (int k = 0; k < MDIM; ++k)
            acc -= Aaug[k * D + i] * Ainv[j * MDIM + k];
    }
    g_P[i * DP + j] = acc;
}

// ---------------- generic small GEMM (front-end MLP, ~0.3ms total) ----------------
#define FLAG_RELU   1
#define FLAG_TRANSB 2
#define FLAG_CONCAT 4
__global__ void gemm16(const float* __restrict__ A, const float* __restrict__ A2,
                       const float* __restrict__ B, const float* __restrict__ bias,
                       float* __restrict__ C, int K, int Nr, int ldc, int flags) {
    __shared__ float As[16][16];
    __shared__ float Bs[16][17];
    int tx = threadIdx.x, ty = threadIdx.y;
    int m = blockIdx.y * 16 + ty;
    int n = blockIdx.x * 16 + tx;
    float acc = 0.f;
    for (int k0 = 0; k0 < K; k0 += 16) {
        int ka = k0 + tx;
        float av = 0.f;
        if (ka < K) {
            if (flags & FLAG_CONCAT) av = (ka < MDIM) ? A[m * MDIM + ka] : A2[m * MDIM + ka - MDIM];
            else                     av = A[m * K + ka];
        }
        As[ty][tx] = av;
        int kb = k0 + ty;
        float bv = 0.f;
        if (kb < K && n < Nr) bv = (flags & FLAG_TRANSB) ? B[n * K + kb] : B[kb * Nr + n];
        Bs[ty][tx] = bv;
        __syncthreads();
#pragma unroll
        for (int kk = 0; kk < 16; ++kk) acc += As[ty][kk] * Bs[kk][tx];
        __syncthreads();
    }
    if (n < ldc) {
        float v = 0.f;
        if (n < Nr) {
            v = acc + (bias ? bias[n] : 0.f);
            if (flags & FLAG_RELU) v = fmaxf(v, 0.f);
        }
        C[m * ldc + n] = v;
    }
}

// ---------------- persistent iteration kernel ----------------
// 128 CTAs x 256 threads. CTA owns 8 batch rows.
// GEMM phase: warp w -> (ch = w&1 column half, kq = w>>1 K quarter).
//   Lane owns cols j = ch*256 + c*128 + lane*4 + {0..3}, c=0..1  (coalesced LDG.128).
//   acc[row 0..7][pair 0..3] f32x2. Each P byte read exactly once per CTA/iter.
// Epilogue phase: warp w -> batch row r=w; lane owns j = s*32 + lane, s=0..15.
// s state: smem i-major duplicated {v,v}, SROW=9 pad; also kept in epilogue regs.
#define RED_OFF   (DP * SROW * 8)                  // 36864
#define Y_OFF     (RED_OFF + 64 * 256 * 4)        // + 65536
#define Q_OFF     (Y_OFF + 8 * DP * 4)            // + 16384
#define SMEM_BYTES (Q_OFF + 8 * DP * 4)           // 135168

__global__ void __launch_bounds__(256, 1) iterate_kernel(float* __restrict__ out) {
    extern __shared__ char smem[];
    ull*   sdup = (ull*)smem;                     // [512][SROW]
    float* redf = (float*)(smem + RED_OFF);       // [(ch*4+kq)*8 + r][256]
    float* yv   = (float*)(smem + Y_OFF);         // [8][512]
    float* qv   = (float*)(smem + Q_OFF);         // [8][512]

    const int tid  = threadIdx.x;
    const int warp = tid >> 5, lane = tid & 31;
    const int ch = warp & 1, kq = warp >> 1;
    const int rowbase = blockIdx.x * 8;

    { // stage y, q; zero s
        const float4* ys = (const float4*)(g_y + rowbase * DP);
        const float4* qs = (const float4*)(g_q + rowbase * DP);
        float4* yd = (float4*)yv; float4* qd = (float4*)qv;
        for (int i = tid; i < 8 * DP / 4; i += 256) { yd[i] = ys[i]; qd[i] = qs[i]; }
        for (int i = tid; i < DP * SROW; i += 256) sdup[i] = 0ull;
    }
    __syncthreads();

    const float OMEGA = 1.8f, TWOSIG = 0.2f, INVC = 1.0f / 1.2f;

    // epilogue-side persistent state (row r = warp, col j = s*32+lane)
    float s_reg[16];
#pragma unroll
    for (int s = 0; s < 16; ++s) s_reg[s] = 0.f;

    // GEMM-side pointers
    const char* Pw = (const char*)(g_P + kq * 128 * DP + ch * 256 + lane * 4);
    const ull* sbase = sdup + kq * 128 * SROW;
    float* redw = redf + (ch * 4 + kq) * 8 * 256 + lane * 4;

    for (int it = 0; it <= ITERS; ++it) {
        // ================= GEMM: acc[r][p] over K quarter =================
        ull acc[8][4];
#pragma unroll
        for (int r = 0; r < 8; ++r)
#pragma unroll
            for (int p = 0; p < 4; ++p) acc[r][p] = 0ull;

        ulonglong2 bufA[2][2], bufB[2][2];

#define LDP(buf, ii)                                                              \
        {                                                                         \
            const char* _p = Pw + (size_t)(ii) * (DP * 4);                        \
            buf[0][0] = *(const ulonglong2*)(_p);                                 \
            buf[0][1] = *(const ulonglong2*)(_p + 128 * 4);                       \
            buf[1][0] = *(const ulonglong2*)(_p + DP * 4);                        \
            buf[1][1] = *(const ulonglong2*)(_p + DP * 4 + 128 * 4);              \
        }

#define COMPUTE(buf, ii)                                                          \
        {                                                                         \
            _Pragma("unroll")                                                     \
            for (int u = 0; u < 2; ++u) {                                         \
                const ull* sc = sbase + ((ii) + u) * SROW;                        \
                ull sd0 = sc[0], sd1 = sc[1], sd2 = sc[2], sd3 = sc[3];           \
                ull sd4 = sc[4], sd5 = sc[5], sd6 = sc[6], sd7 = sc[7];           \
                ull p0 = buf[u][0].x, p1 = buf[u][0].y;                           \
                ull p2 = buf[u][1].x, p3 = buf[u][1].y;                           \
                ffma2(acc[0][0], sd0, p0); ffma2(acc[0][1], sd0, p1);             \
                ffma2(acc[0][2], sd0, p2); ffma2(acc[0][3], sd0, p3);             \
                ffma2(acc[1][0], sd1, p0); ffma2(acc[1][1], sd1, p1);             \
                ffma2(acc[1][2], sd1, p2); ffma2(acc[1][3], sd1, p3);             \
                ffma2(acc[2][0], sd2, p0); ffma2(acc[2][1], sd2, p1);             \
                ffma2(acc[2][2], sd2, p2); ffma2(acc[2][3], sd2, p3);             \
                ffma2(acc[3][0], sd3, p0); ffma2(acc[3][1], sd3, p1);             \
                ffma2(acc[3][2], sd3, p2); ffma2(acc[3][3], sd3, p3);             \
                ffma2(acc[4][0], sd4, p0); ffma2(acc[4][1], sd4, p1);             \
                ffma2(acc[4][2], sd4, p2); ffma2(acc[4][3], sd4, p3);             \
                ffma2(acc[5][0], sd5, p0); ffma2(acc[5][1], sd5, p1);             \
                ffma2(acc[5][2], sd5, p2); ffma2(acc[5][3], sd5, p3);             \
                ffma2(acc[6][0], sd6, p0); ffma2(acc[6][1], sd6, p1);             \
                ffma2(acc[6][2], sd6, p2); ffma2(acc[6][3], sd6, p3);             \
                ffma2(acc[7][0], sd7, p0); ffma2(acc[7][1], sd7, p1);             \
                ffma2(acc[7][2], sd7, p2); ffma2(acc[7][3], sd7, p3);             \
            }                                                                     \
        }

        LDP(bufA, 0);
#pragma unroll 1
        for (int sb = 0; sb < 64; sb += 2) {
            LDP(bufB, (sb + 1) * 2);
            COMPUTE(bufA, sb * 2);
            LDP(bufA, ((sb + 2) * 2) & 127);   // wraps harmlessly on last iter
            COMPUTE(bufB, (sb + 1) * 2);
        }

        // write partials to red: [ (ch*4+kq)*8 + r ][256], float4 per (r,c)
#pragma unroll
        for (int r = 0; r < 8; ++r) {
#pragma unroll
            for (int c = 0; c < 2; ++c) {
                float2 a = unpk(acc[r][2 * c]), b = unpk(acc[r][2 * c + 1]);
                float4 v; v.x = a.x; v.y = a.y; v.z = b.x; v.w = b.y;
                *(float4*)(redw + r * 256 + c * 128) = v;
            }
        }
        __syncthreads();

        // ================= epilogue: warp = row r, lane col j = s*32+lane ====
        const int r = warp;
        float z[16];
#pragma unroll
        for (int s = 0; s < 16; ++s) {
            int j  = s * 32 + lane;
            int jc = j & 255, chj = j >> 8;
            const float* rb = redf + (chj * 4) * 8 * 256 + r * 256 + jc;
            float g = rb[0] + rb[8 * 256] + rb[16 * 256] + rb[24 * 256];
            z[s] = g + qv[r * DP + j];
        }

        if (it == ITERS) {
            const int gr = rowbase + r;
#pragma unroll
            for (int s = 0; s < 16; ++s) {
                int j = s * 32 + lane;
                if (j < D) out[gr * D + j] = z[s];
            }
            break;
        }

        float tp[16];
#pragma unroll
        for (int s = 0; s < 16; ++s) {
            int j = s * 32 + lane;
            tp[s] = (2.f * z[s] - s_reg[s] - TWOSIG * yv[r * DP + j]) * INVC;
        }
        // ||u||^2 over j in [250, 499)
        float part = 0.f;
#pragma unroll
        for (int s = 0; s < 16; ++s) {
            int j = s * 32 + lane;
            if (j >= NDIM && j < D - 1) part += tp[s] * tp[s];
        }
#pragma unroll
        for (int o = 16; o > 0; o >>= 1) part += __shfl_xor_sync(0xffffffffu, part, o);
        float nrm  = sqrtf(part);
        float tval = __shfl_sync(0xffffffffu, tp[15], 19);  // j=499 = 15*32+19
        float f3 = 0.5f * (tval + nrm);
        float fu = f3 / (nrm + 1e-12f);
        bool case1 = (nrm <= tval);
        bool case2 = (!case1) && (nrm <= -tval);
#pragma unroll
        for (int s = 0; s < 16; ++s) {
            int j = s * 32 + lane;
            float tk;
            if      (j < NDIM)   tk = tp[s];
            else if (j < D - 1)  tk = case1 ? tp[s] : (case2 ? 0.f : fu * tp[s]);
            else if (j == D - 1) tk = case1 ? tp[s] : (case2 ? 0.f : f3);
            else                 tk = 0.f;
            float sn = s_reg[s] + OMEGA * (tk - z[s]);
            s_reg[s] = sn;
            sdup[j * SROW + r] = dup2(sn);
        }
        __syncthreads();
    }
#undef LDP
#undef COMPUTE
}

// ---------------- launch ----------------
extern "C" void kernel_launch(void* const* d_in, const int* in_sizes, int n_in,
                              void* d_out, int out_size) {
    const float* b    = (const float*)d_in[0];
    const float* c    = (const float*)d_in[1];
    const float* W1   = (const float*)d_in[2];
    const float* b1   = (const float*)d_in[3];
    const float* W2   = (const float*)d_in[4];
    const float* b2   = (const float*)d_in[5];
    const float* W3   = (const float*)d_in[6];
    const float* b3   = (const float*)d_in[7];
    const float* Aaug = (const float*)d_in[8];
    const float* Ainv = (const float*)d_in[9];
    float* out = (float*)d_out;

    void *p;
    cudaGetSymbolAddress(&p, g_h1); float* h1 = (float*)p;
    cudaGetSymbolAddress(&p, g_h2); float* h2 = (float*)p;
    cudaGetSymbolAddress(&p, g_y ); float* yy = (float*)p;
    cudaGetSymbolAddress(&p, g_q ); float* qq = (float*)p;

    computeP<<<(DP * DP) / 256, 256>>>(Aaug, Ainv);

    dim3 tb(16, 16);
    gemm16<<<dim3(HDIM / 16, BATCH / 16), tb>>>(b, c, W1, b1, h1, 500, HDIM, HDIM, FLAG_RELU | FLAG_CONCAT);
    gemm16<<<dim3(HDIM / 16, BATCH / 16), tb>>>(h1, nullptr, W2, b2, h2, HDIM, HDIM, HDIM, FLAG_RELU);
    gemm16<<<dim3(DP / 16, BATCH / 16), tb>>>(h2, nullptr, W3, b3, yy, HDIM, D, DP, 0);
    gemm16<<<dim3(DP / 16, BATCH / 16), tb>>>(b, nullptr, Ainv, nullptr, qq, MDIM, D, DP, FLAG_TRANSB);

    cudaFuncSetAttribute(iterate_kernel, cudaFuncAttributeMaxDynamicSharedMemorySize, SMEM_BYTES);
    iterate_kernel<<<BATCH / 8, 256, SMEM_BYTES>>>(out);
}